// round 4
// baseline (speedup 1.0000x reference)
#include <cuda_runtime.h>
#include <cuda_bf16.h>
#include <cstdint>
#include <math.h>

#define N_IN   256
#define N_OUT  64
#define TM     256            // rows per GEMM CTA (32 per warp x 8 warps)
#define XS_STRIDE 68          // x tile smem stride (floats) — conflict-free A frags

// Scratch for h = x@W + b  (100000 x 64 floats = 25.6 MB)
__device__ float g_h[100000 * N_OUT];
// W fragment table: [k8=32][tig=4][g=8][16 floats] = 16384 floats = 64 KB
__device__ float g_wfrag[32 * 4 * 8 * 16];

#define XS_FLOATS (TM * XS_STRIDE)
#define GEMM_SMEM (XS_FLOATS * 4)        // 256*68*4 = 69632 B

__device__ __forceinline__ float to_tf32(float f) {
    uint32_t r;
    asm("cvt.rna.tf32.f32 %0, %1;" : "=r"(r) : "f"(f));
    return __uint_as_float(r);
}

// ===========================================================================
// zero the output accumulator (d_out is poisoned with 0xAA)
// ===========================================================================
__global__ void zero_kernel(float4* __restrict__ out, int n4) {
    int i = blockIdx.x * blockDim.x + threadIdx.x;
    if (i < n4) out[i] = make_float4(0.f, 0.f, 0.f, 0.f);
}

// ===========================================================================
// Build per-thread B-fragment table from W (row-major [256][64]), tf32-rounded.
// Entry layout: idx = ((k8*4 + tig)*8 + g)*16 + (nt*2 + half)
//   value = W[k8*8 + tig + half*4][nt*8 + g]
// ===========================================================================
__global__ void wfrag_kernel(const float* __restrict__ W) {
    int i = blockIdx.x * blockDim.x + threadIdx.x;
    if (i < 32 * 4 * 8 * 16) {
        const int j    = i & 15;
        const int g    = (i >> 4) & 7;
        const int tig  = (i >> 7) & 3;
        const int k8   = i >> 9;
        const int nt   = j >> 1;
        const int half = j & 1;
        g_wfrag[i] = to_tf32(W[(size_t)(k8 * 8 + tig + half * 4) * N_OUT + nt * 8 + g]);
    }
}

// ===========================================================================
// GEMM via mma.sync m16n8k8 tf32: h[N,64] = x[N,256] @ W[256,64] + b
// CTA: 256 threads = 8 warps; warp w owns rows [w*32, w*32+32), all 64 cols
// (two m16 row tiles). B fragments come straight from g_wfrag via LDG.128.
// ===========================================================================
__global__ void __launch_bounds__(256) gemm_mma_kernel(
    const float* __restrict__ x, const float* __restrict__ b, int N)
{
    extern __shared__ float xs[];    // [256][XS_STRIDE]

    const int tid  = threadIdx.x;
    const int w    = tid >> 5;
    const int lane = tid & 31;
    const int g    = lane >> 2;      // 0..7
    const int tig  = lane & 3;       // 0..3
    const int block_row = blockIdx.x * TM;

    float acc0[8][4], acc1[8][4];
#pragma unroll
    for (int nt = 0; nt < 8; nt++)
#pragma unroll
        for (int j = 0; j < 4; j++) { acc0[nt][j] = 0.f; acc1[nt][j] = 0.f; }

    const float4* wf_base =
        (const float4*)(g_wfrag) + ((size_t)tig * 8 + g) * 4;  // + k32*32 float4

    for (int kc = 0; kc < 4; kc++) {
        // ---- stage x chunk: 256 rows x 64 k (4096 float4, 16 per thread) ----
#pragma unroll
        for (int p = 0; p < 16; p++) {
            const int id  = tid + p * 256;
            const int row = id >> 4;
            const int f4  = id & 15;
            int grow = block_row + row;
            if (grow >= N) grow = N - 1;                  // clamp, result unused
            float4 v = *(const float4*)(x + (size_t)grow * N_IN + kc * 64 + f4 * 4);
            float* dst = &xs[row * XS_STRIDE + f4 * 4];
            dst[0] = to_tf32(v.x); dst[1] = to_tf32(v.y);
            dst[2] = to_tf32(v.z); dst[3] = to_tf32(v.w);
        }
        __syncthreads();

#pragma unroll
        for (int k8 = 0; k8 < 8; k8++) {
            const int kb = k8 * 8;
            const int k32 = kc * 8 + k8;

            // B fragments: 4 x LDG.128 from the shared table (L1/L2 resident)
            const float4* fp = wf_base + (size_t)k32 * 128;  // 4*8*4 float4 per k32
            const float4 f0 = fp[0], f1 = fp[1], f2 = fp[2], f3 = fp[3];

            // A fragments: two m16 row tiles, conflict-free scalar LDS
            const int rb = w * 32 + g;
            const uint32_t a00 = __float_as_uint(xs[(rb     ) * XS_STRIDE + kb + tig]);
            const uint32_t a01 = __float_as_uint(xs[(rb +  8) * XS_STRIDE + kb + tig]);
            const uint32_t a02 = __float_as_uint(xs[(rb     ) * XS_STRIDE + kb + tig + 4]);
            const uint32_t a03 = __float_as_uint(xs[(rb +  8) * XS_STRIDE + kb + tig + 4]);
            const uint32_t a10 = __float_as_uint(xs[(rb + 16) * XS_STRIDE + kb + tig]);
            const uint32_t a11 = __float_as_uint(xs[(rb + 24) * XS_STRIDE + kb + tig]);
            const uint32_t a12 = __float_as_uint(xs[(rb + 16) * XS_STRIDE + kb + tig + 4]);
            const uint32_t a13 = __float_as_uint(xs[(rb + 24) * XS_STRIDE + kb + tig + 4]);

            const float4 fr[4] = {f0, f1, f2, f3};
#pragma unroll
            for (int nt = 0; nt < 8; nt++) {
                const float4 f = fr[nt >> 1];
                const uint32_t b0 = __float_as_uint((nt & 1) ? f.z : f.x);
                const uint32_t b1 = __float_as_uint((nt & 1) ? f.w : f.y);
                asm volatile(
                    "mma.sync.aligned.m16n8k8.row.col.f32.tf32.tf32.f32 "
                    "{%0, %1, %2, %3}, {%4, %5, %6, %7}, {%8, %9}, "
                    "{%0, %1, %2, %3};"
                    : "+f"(acc0[nt][0]), "+f"(acc0[nt][1]),
                      "+f"(acc0[nt][2]), "+f"(acc0[nt][3])
                    : "r"(a00), "r"(a01), "r"(a02), "r"(a03), "r"(b0), "r"(b1));
                asm volatile(
                    "mma.sync.aligned.m16n8k8.row.col.f32.tf32.tf32.f32 "
                    "{%0, %1, %2, %3}, {%4, %5, %6, %7}, {%8, %9}, "
                    "{%0, %1, %2, %3};"
                    : "+f"(acc1[nt][0]), "+f"(acc1[nt][1]),
                      "+f"(acc1[nt][2]), "+f"(acc1[nt][3])
                    : "r"(a10), "r"(a11), "r"(a12), "r"(a13), "r"(b0), "r"(b1));
            }
        }
        __syncthreads();
    }

    // ---- epilogue: bias add, store to g_h ----
    const int r0 = block_row + w * 32 + g;
#pragma unroll
    for (int nt = 0; nt < 8; nt++) {
        const int col = nt * 8 + 2 * tig;
        const float bx = b[col], by = b[col + 1];
        if (r0 < N)
            *(float2*)(g_h + (size_t)r0 * N_OUT + col) =
                make_float2(acc0[nt][0] + bx, acc0[nt][1] + by);
        if (r0 + 8 < N)
            *(float2*)(g_h + (size_t)(r0 + 8) * N_OUT + col) =
                make_float2(acc0[nt][2] + bx, acc0[nt][3] + by);
        if (r0 + 16 < N)
            *(float2*)(g_h + (size_t)(r0 + 16) * N_OUT + col) =
                make_float2(acc1[nt][0] + bx, acc1[nt][1] + by);
        if (r0 + 24 < N)
            *(float2*)(g_h + (size_t)(r0 + 24) * N_OUT + col) =
                make_float2(acc1[nt][2] + bx, acc1[nt][3] + by);
    }
}

// ===========================================================================
// Edge scatter: out[row] += val * h[col]. 16 lanes per edge, one float4 slice
// per lane, red.global.add.v4.f32 (no return).
// ===========================================================================
__global__ void __launch_bounds__(256) scatter_kernel(
    const int* __restrict__ rows, const int* __restrict__ cols,
    const float* __restrict__ vals, float* __restrict__ out, int E)
{
    const int gtid = blockIdx.x * blockDim.x + threadIdx.x;
    const int e    = gtid >> 4;
    const int lane = gtid & 15;
    if (e >= E) return;

    const int   r = rows[e];
    const int   c = cols[e];
    const float v = vals[e];

    float4 m = *((const float4*)(g_h + (size_t)c * N_OUT) + lane);
    m.x *= v; m.y *= v; m.z *= v; m.w *= v;

    float* o = out + (size_t)r * N_OUT + lane * 4;
    asm volatile("red.global.add.v4.f32 [%0], {%1, %2, %3, %4};"
                 :: "l"(o), "f"(m.x), "f"(m.y), "f"(m.z), "f"(m.w)
                 : "memory");
}

// ===========================================================================
// ELU epilogue, float4-vectorized
// ===========================================================================
__global__ void elu_kernel(float4* __restrict__ out, int n4) {
    int i = blockIdx.x * blockDim.x + threadIdx.x;
    if (i < n4) {
        float4 v = out[i];
        v.x = v.x > 0.f ? v.x : expm1f(v.x);
        v.y = v.y > 0.f ? v.y : expm1f(v.y);
        v.z = v.z > 0.f ? v.z : expm1f(v.z);
        v.w = v.w > 0.f ? v.w : expm1f(v.w);
        out[i] = v;
    }
}

// ===========================================================================
extern "C" void kernel_launch(void* const* d_in, const int* in_sizes, int n_in,
                              void* d_out, int out_size)
{
    const float* x  = (const float*)d_in[0];
    const int*   er = (const int*)  d_in[1];
    const int*   ec = (const int*)  d_in[2];
    const float* ev = (const float*)d_in[3];
    const float* W  = (const float*)d_in[4];
    const float* b  = (const float*)d_in[5];
    float* out = (float*)d_out;

    const int N = in_sizes[0] / N_IN;   // 100000
    const int E = in_sizes[1];          // 1600000
    const int n_out_elems = N * N_OUT;

    static bool attr_set = false;
    if (!attr_set) {
        cudaFuncSetAttribute(gemm_mma_kernel,
                             cudaFuncAttributeMaxDynamicSharedMemorySize, GEMM_SMEM);
        attr_set = true;
    }

    // 1) zero accumulator
    {
        int n4 = n_out_elems / 4;
        zero_kernel<<<(n4 + 255) / 256, 256>>>((float4*)out, n4);
    }
    // 2a) build W fragment table
    wfrag_kernel<<<64, 256>>>(W);
    // 2b) h = x @ W + b  (mma.sync tf32, B frags from gmem table)
    gemm_mma_kernel<<<(N + TM - 1) / TM, 256, GEMM_SMEM>>>(x, b, N);
    // 3) out[row] += val * h[col] over all edges
    {
        long long total = (long long)E * 16;
        int blocks = (int)((total + 255) / 256);
        scatter_kernel<<<blocks, 256>>>(er, ec, ev, out, E);
    }
    // 4) ELU in place (vectorized)
    elu_kernel<<<(n_out_elems / 4 + 255) / 256, 256>>>((float4*)out, n_out_elems / 4);
}

// round 5
// speedup vs baseline: 1.1818x; 1.1818x over previous
#include <cuda_runtime.h>
#include <cuda_bf16.h>
#include <cstdint>
#include <math.h>

#define N_IN   256
#define N_OUT  64
#define TM     128            // rows per GEMM CTA
#define XS_STRIDE 68          // x tile smem stride (floats)
#define WS_STRIDE 72          // W tile smem stride (floats)

#define MAX_N  100000
#define MAX_E  1600000
#define SCAN_BLK 512

// Scratch
__device__ float g_h[MAX_N * N_OUT];         // h = x@W + b
__device__ int   g_deg[MAX_N];
__device__ int   g_bsum[256];
__device__ int   g_rowptr[MAX_N + 1];
__device__ int   g_cursor[MAX_N];
__device__ int   g_ecol[MAX_E];
__device__ float g_eval[MAX_E];

// dynamic smem for GEMM: xs[128][68] + ws[256][72]
#define XS_FLOATS (TM * XS_STRIDE)
#define WS_FLOATS (256 * WS_STRIDE)
#define GEMM_SMEM ((XS_FLOATS + WS_FLOATS) * 4)

__device__ __forceinline__ float to_tf32(float f) {
    uint32_t r;
    asm("cvt.rna.tf32.f32 %0, %1;" : "=r"(r) : "f"(f));
    return __uint_as_float(r);
}

// ===========================================================================
// CSR build
// ===========================================================================
__global__ void deg_zero_kernel(int n) {
    int i = blockIdx.x * blockDim.x + threadIdx.x;
    if (i < n) g_deg[i] = 0;
}

__global__ void hist_kernel(const int* __restrict__ rows, int E) {
    int e = blockIdx.x * blockDim.x + threadIdx.x;
    if (e < E) atomicAdd(&g_deg[rows[e]], 1);
}

__global__ void __launch_bounds__(SCAN_BLK) bsum_kernel(int n) {
    __shared__ int s[SCAN_BLK];
    const int t = threadIdx.x;
    const int i = blockIdx.x * SCAN_BLK + t;
    s[t] = (i < n) ? g_deg[i] : 0;
    __syncthreads();
#pragma unroll
    for (int st = SCAN_BLK / 2; st > 0; st >>= 1) {
        if (t < st) s[t] += s[t + st];
        __syncthreads();
    }
    if (t == 0) g_bsum[blockIdx.x] = s[0];
}

__global__ void __launch_bounds__(256) scan_bsum_kernel(int nb) {
    __shared__ int s[256];
    const int t = threadIdx.x;
    const int v = (t < nb) ? g_bsum[t] : 0;
    s[t] = v;
    __syncthreads();
#pragma unroll
    for (int off = 1; off < 256; off <<= 1) {
        int add = (t >= off) ? s[t - off] : 0;
        __syncthreads();
        s[t] += add;
        __syncthreads();
    }
    if (t < nb) g_bsum[t] = s[t] - v;   // exclusive
}

__global__ void __launch_bounds__(SCAN_BLK) scan_local_kernel(int n, int E) {
    __shared__ int s[SCAN_BLK];
    const int t = threadIdx.x;
    const int i = blockIdx.x * SCAN_BLK + t;
    const int v = (i < n) ? g_deg[i] : 0;
    s[t] = v;
    __syncthreads();
#pragma unroll
    for (int off = 1; off < SCAN_BLK; off <<= 1) {
        int add = (t >= off) ? s[t - off] : 0;
        __syncthreads();
        s[t] += add;
        __syncthreads();
    }
    const int excl = s[t] - v;
    const int base = g_bsum[blockIdx.x];
    if (i < n) {
        g_rowptr[i] = base + excl;
        g_cursor[i] = base + excl;
    }
    if (i == n - 1) g_rowptr[n] = E;
}

__global__ void fill_kernel(const int* __restrict__ rows,
                            const int* __restrict__ cols,
                            const float* __restrict__ vals, int E) {
    int e = blockIdx.x * blockDim.x + threadIdx.x;
    if (e < E) {
        int p = atomicAdd(&g_cursor[rows[e]], 1);
        g_ecol[p] = cols[e];
        g_eval[p] = vals[e];
    }
}

// ===========================================================================
// GEMM via mma.sync m16n8k8 tf32: h[N,64] = x[N,256] @ W[256,64] + b
// (R3 configuration: 8 warps x 16 rows, W staged once in smem)
// ===========================================================================
__global__ void __launch_bounds__(256) gemm_mma_kernel(
    const float* __restrict__ x, const float* __restrict__ W,
    const float* __restrict__ b, int N)
{
    extern __shared__ float smem[];
    float* xs = smem;                // [128][XS_STRIDE]
    float* ws = smem + XS_FLOATS;    // [256][WS_STRIDE]

    const int tid  = threadIdx.x;
    const int w    = tid >> 5;
    const int lane = tid & 31;
    const int g    = lane >> 2;
    const int tig  = lane & 3;
    const int block_row = blockIdx.x * TM;

    for (int id = tid; id < 256 * 16; id += 256) {
        const int row = id >> 4;
        const int f4  = id & 15;
        float4 v = *(const float4*)(W + (size_t)row * N_OUT + f4 * 4);
        v.x = to_tf32(v.x); v.y = to_tf32(v.y);
        v.z = to_tf32(v.z); v.w = to_tf32(v.w);
        *(float4*)&ws[row * WS_STRIDE + f4 * 4] = v;
    }

    float acc[8][4];
#pragma unroll
    for (int nt = 0; nt < 8; nt++)
#pragma unroll
        for (int j = 0; j < 4; j++) acc[nt][j] = 0.f;

    for (int kc = 0; kc < 4; kc++) {
#pragma unroll
        for (int p = 0; p < 8; p++) {
            const int id  = tid + p * 256;
            const int row = id >> 4;
            const int f4  = id & 15;
            int grow = block_row + row;
            if (grow >= N) grow = N - 1;
            float4 v = *(const float4*)(x + (size_t)grow * N_IN + kc * 64 + f4 * 4);
            float* dst = &xs[row * XS_STRIDE + f4 * 4];
            dst[0] = to_tf32(v.x); dst[1] = to_tf32(v.y);
            dst[2] = to_tf32(v.z); dst[3] = to_tf32(v.w);
        }
        __syncthreads();

#pragma unroll
        for (int k8 = 0; k8 < 8; k8++) {
            const int kb = k8 * 8;
            const int r0 = (w * 16 + g) * XS_STRIDE;
            const int r1 = (w * 16 + g + 8) * XS_STRIDE;
            const uint32_t a0 = __float_as_uint(xs[r0 + kb + tig]);
            const uint32_t a1 = __float_as_uint(xs[r1 + kb + tig]);
            const uint32_t a2 = __float_as_uint(xs[r0 + kb + tig + 4]);
            const uint32_t a3 = __float_as_uint(xs[r1 + kb + tig + 4]);

            const int krow = kc * 64 + kb;
#pragma unroll
            for (int nt = 0; nt < 8; nt++) {
                const uint32_t b0 =
                    __float_as_uint(ws[(krow + tig) * WS_STRIDE + nt * 8 + g]);
                const uint32_t b1 =
                    __float_as_uint(ws[(krow + tig + 4) * WS_STRIDE + nt * 8 + g]);
                asm volatile(
                    "mma.sync.aligned.m16n8k8.row.col.f32.tf32.tf32.f32 "
                    "{%0, %1, %2, %3}, {%4, %5, %6, %7}, {%8, %9}, "
                    "{%0, %1, %2, %3};"
                    : "+f"(acc[nt][0]), "+f"(acc[nt][1]),
                      "+f"(acc[nt][2]), "+f"(acc[nt][3])
                    : "r"(a0), "r"(a1), "r"(a2), "r"(a3), "r"(b0), "r"(b1));
            }
        }
        __syncthreads();
    }

    const int row0 = block_row + w * 16 + g;
    const int row1 = row0 + 8;
#pragma unroll
    for (int nt = 0; nt < 8; nt++) {
        const int col = nt * 8 + 2 * tig;
        const float bx = b[col], by = b[col + 1];
        if (row0 < N)
            *(float2*)(g_h + (size_t)row0 * N_OUT + col) =
                make_float2(acc[nt][0] + bx, acc[nt][1] + by);
        if (row1 < N)
            *(float2*)(g_h + (size_t)row1 * N_OUT + col) =
                make_float2(acc[nt][2] + bx, acc[nt][3] + by);
    }
}

// ===========================================================================
// Gather aggregation + fused ELU: out[i] = elu(sum_e val[e] * h[col[e]])
// 16 lanes per node, one float4 slice each; edge loop unrolled x4 for MLP.
// ===========================================================================
__global__ void __launch_bounds__(256) gather_kernel(float* __restrict__ out, int N)
{
    const int gtid = blockIdx.x * blockDim.x + threadIdx.x;
    const int node = gtid >> 4;
    const int lane = gtid & 15;
    if (node >= N) return;

    int beg = g_rowptr[node];
    const int end = g_rowptr[node + 1];

    float4 acc = make_float4(0.f, 0.f, 0.f, 0.f);

    for (; beg + 4 <= end; beg += 4) {
        const int   c0 = g_ecol[beg],     c1 = g_ecol[beg + 1];
        const int   c2 = g_ecol[beg + 2], c3 = g_ecol[beg + 3];
        const float v0 = g_eval[beg],     v1 = g_eval[beg + 1];
        const float v2 = g_eval[beg + 2], v3 = g_eval[beg + 3];
        const float4 m0 = *((const float4*)(g_h + (size_t)c0 * N_OUT) + lane);
        const float4 m1 = *((const float4*)(g_h + (size_t)c1 * N_OUT) + lane);
        const float4 m2 = *((const float4*)(g_h + (size_t)c2 * N_OUT) + lane);
        const float4 m3 = *((const float4*)(g_h + (size_t)c3 * N_OUT) + lane);
        acc.x += v0 * m0.x; acc.y += v0 * m0.y; acc.z += v0 * m0.z; acc.w += v0 * m0.w;
        acc.x += v1 * m1.x; acc.y += v1 * m1.y; acc.z += v1 * m1.z; acc.w += v1 * m1.w;
        acc.x += v2 * m2.x; acc.y += v2 * m2.y; acc.z += v2 * m2.z; acc.w += v2 * m2.w;
        acc.x += v3 * m3.x; acc.y += v3 * m3.y; acc.z += v3 * m3.z; acc.w += v3 * m3.w;
    }
    for (; beg < end; beg++) {
        const int   c = g_ecol[beg];
        const float v = g_eval[beg];
        const float4 m = *((const float4*)(g_h + (size_t)c * N_OUT) + lane);
        acc.x += v * m.x; acc.y += v * m.y; acc.z += v * m.z; acc.w += v * m.w;
    }

    // ELU (alpha=1)
    acc.x = acc.x > 0.f ? acc.x : expm1f(acc.x);
    acc.y = acc.y > 0.f ? acc.y : expm1f(acc.y);
    acc.z = acc.z > 0.f ? acc.z : expm1f(acc.z);
    acc.w = acc.w > 0.f ? acc.w : expm1f(acc.w);

    *((float4*)(out + (size_t)node * N_OUT) + lane) = acc;
}

// ===========================================================================
extern "C" void kernel_launch(void* const* d_in, const int* in_sizes, int n_in,
                              void* d_out, int out_size)
{
    const float* x  = (const float*)d_in[0];
    const int*   er = (const int*)  d_in[1];
    const int*   ec = (const int*)  d_in[2];
    const float* ev = (const float*)d_in[3];
    const float* W  = (const float*)d_in[4];
    const float* b  = (const float*)d_in[5];
    float* out = (float*)d_out;

    const int N = in_sizes[0] / N_IN;   // 100000
    const int E = in_sizes[1];          // 1600000
    const int NB = (N + SCAN_BLK - 1) / SCAN_BLK;   // 196

    static bool attr_set = false;
    if (!attr_set) {
        cudaFuncSetAttribute(gemm_mma_kernel,
                             cudaFuncAttributeMaxDynamicSharedMemorySize, GEMM_SMEM);
        attr_set = true;
    }

    // --- CSR build ---
    deg_zero_kernel<<<(N + 511) / 512, 512>>>(N);
    hist_kernel<<<(E + 255) / 256, 256>>>(er, E);
    bsum_kernel<<<NB, SCAN_BLK>>>(N);
    scan_bsum_kernel<<<1, 256>>>(NB);
    scan_local_kernel<<<NB, SCAN_BLK>>>(N, E);
    fill_kernel<<<(E + 255) / 256, 256>>>(er, ec, ev, E);

    // --- h = x @ W + b ---
    gemm_mma_kernel<<<(N + TM - 1) / TM, 256, GEMM_SMEM>>>(x, W, b, N);

    // --- out = elu(A @ h) via CSR gather ---
    {
        long long total = (long long)N * 16;
        int blocks = (int)((total + 255) / 256);
        gather_kernel<<<blocks, 256>>>(out, N);
    }
}

// round 6
// speedup vs baseline: 1.4132x; 1.1958x over previous
#include <cuda_runtime.h>
#include <cuda_fp16.h>
#include <cuda_bf16.h>
#include <cstdint>
#include <math.h>

#define N_IN   256
#define N_OUT  64
#define TM     128            // rows per GEMM CTA
#define XS_STRIDE 72          // x tile smem stride in halves (64 k + pad)
#define WS_STRIDE 264         // W^T smem stride in halves (256 k + pad)

#define MAX_N  100000
#define MAX_E  1600000
#define SCAN_BLK 512

// Scratch
__device__ float    g_h[MAX_N * N_OUT];      // h = x@W + b
__device__ __half   g_wht[N_OUT * N_IN];     // W^T in fp16: [n][k]
__device__ int      g_deg[MAX_N];
__device__ int      g_bsum[256];
__device__ int      g_rowptr[MAX_N + 1];
__device__ int      g_cursor[MAX_N];
__device__ int      g_ecol[MAX_E];
__device__ float    g_eval[MAX_E];

// dynamic smem: xs[128][72] halves + ws[64][264] halves
#define XS_HALVES (TM * XS_STRIDE)           // 9216
#define WS_HALVES (N_OUT * WS_STRIDE)        // 16896
#define GEMM_SMEM ((XS_HALVES + WS_HALVES) * 2)   // 52224 B

// ===========================================================================
// CSR build
// ===========================================================================
__global__ void deg_zero_kernel(int n) {
    int i = blockIdx.x * blockDim.x + threadIdx.x;
    if (i < n) g_deg[i] = 0;
}

__global__ void hist_kernel(const int* __restrict__ rows, int E) {
    int e = blockIdx.x * blockDim.x + threadIdx.x;
    if (e < E) atomicAdd(&g_deg[rows[e]], 1);
}

__global__ void __launch_bounds__(SCAN_BLK) bsum_kernel(int n) {
    __shared__ int s[SCAN_BLK];
    const int t = threadIdx.x;
    const int i = blockIdx.x * SCAN_BLK + t;
    s[t] = (i < n) ? g_deg[i] : 0;
    __syncthreads();
#pragma unroll
    for (int st = SCAN_BLK / 2; st > 0; st >>= 1) {
        if (t < st) s[t] += s[t + st];
        __syncthreads();
    }
    if (t == 0) g_bsum[blockIdx.x] = s[0];
}

__global__ void __launch_bounds__(256) scan_bsum_kernel(int nb) {
    __shared__ int s[256];
    const int t = threadIdx.x;
    const int v = (t < nb) ? g_bsum[t] : 0;
    s[t] = v;
    __syncthreads();
#pragma unroll
    for (int off = 1; off < 256; off <<= 1) {
        int add = (t >= off) ? s[t - off] : 0;
        __syncthreads();
        s[t] += add;
        __syncthreads();
    }
    if (t < nb) g_bsum[t] = s[t] - v;   // exclusive
}

__global__ void __launch_bounds__(SCAN_BLK) scan_local_kernel(int n, int E) {
    __shared__ int s[SCAN_BLK];
    const int t = threadIdx.x;
    const int i = blockIdx.x * SCAN_BLK + t;
    const int v = (i < n) ? g_deg[i] : 0;
    s[t] = v;
    __syncthreads();
#pragma unroll
    for (int off = 1; off < SCAN_BLK; off <<= 1) {
        int add = (t >= off) ? s[t - off] : 0;
        __syncthreads();
        s[t] += add;
        __syncthreads();
    }
    const int excl = s[t] - v;
    const int base = g_bsum[blockIdx.x];
    if (i < n) {
        g_rowptr[i] = base + excl;
        g_cursor[i] = base + excl;
    }
    if (i == n - 1) g_rowptr[n] = E;
}

__global__ void fill_kernel(const int* __restrict__ rows,
                            const int* __restrict__ cols,
                            const float* __restrict__ vals, int E) {
    int e = blockIdx.x * blockDim.x + threadIdx.x;
    if (e < E) {
        int p = atomicAdd(&g_cursor[rows[e]], 1);
        g_ecol[p] = cols[e];
        g_eval[p] = vals[e];
    }
}

// ===========================================================================
// W^T fp16 prep: g_wht[n][k] = fp16(W[k][n])
// ===========================================================================
__global__ void wht_kernel(const float* __restrict__ W) {
    int i = blockIdx.x * blockDim.x + threadIdx.x;
    if (i < N_OUT * N_IN) {
        const int n = i >> 8;
        const int k = i & 255;
        g_wht[i] = __float2half_rn(W[(size_t)k * N_OUT + n]);
    }
}

// ===========================================================================
// GEMM via mma.sync m16n8k16 fp16 (fp32 accum): h[N,64] = x[N,256]@W + b
// CTA: 256 threads = 8 warps; warp w owns rows [w*16, w*16+16), all 64 cols.
// W^T staged once (fp16, [n][k]); x staged in 4 chunks of 128 rows x 64 k.
// ===========================================================================
__global__ void __launch_bounds__(256) gemm_mma_kernel(
    const float* __restrict__ x, const float* __restrict__ b, int N)
{
    extern __shared__ uint16_t smem_h[];
    uint16_t* xs = smem_h;               // [128][XS_STRIDE]
    uint16_t* ws = smem_h + XS_HALVES;   // [64][WS_STRIDE]

    const int tid  = threadIdx.x;
    const int w    = tid >> 5;
    const int lane = tid & 31;
    const int g    = lane >> 2;          // 0..7
    const int tig  = lane & 3;           // 0..3
    const int block_row = blockIdx.x * TM;

    // ---- stage W^T: 64 rows x 256 k halves, uint4 copy (2048 uint4) ----
    for (int i = tid; i < N_OUT * 32; i += 256) {
        const int n = i >> 5;
        const int j = i & 31;
        *(uint4*)&ws[n * WS_STRIDE + j * 8] = ((const uint4*)g_wht)[n * 32 + j];
    }

    float acc[8][4];
#pragma unroll
    for (int nt = 0; nt < 8; nt++)
#pragma unroll
        for (int j = 0; j < 4; j++) acc[nt][j] = 0.f;

    for (int kc = 0; kc < 4; kc++) {
        // ---- stage x chunk: 128 rows x 64 k, fp32 -> fp16 (2048 float4) ----
#pragma unroll
        for (int p = 0; p < 8; p++) {
            const int id  = tid + p * 256;
            const int row = id >> 4;
            const int f4  = id & 15;
            int grow = block_row + row;
            if (grow >= N) grow = N - 1;                  // clamp, result unused
            float4 v = *(const float4*)(x + (size_t)grow * N_IN + kc * 64 + f4 * 4);
            __half2 h01 = __float22half2_rn(make_float2(v.x, v.y));
            __half2 h23 = __float22half2_rn(make_float2(v.z, v.w));
            uint2 pk;
            pk.x = *(const uint32_t*)&h01;
            pk.y = *(const uint32_t*)&h23;
            *(uint2*)&xs[row * XS_STRIDE + f4 * 4] = pk;
        }
        __syncthreads();

#pragma unroll
        for (int k16 = 0; k16 < 4; k16++) {
            const int kb = k16 * 16;
            const int kglob = kc * 64 + kb;

            // A fragments: 4 half2 LDS (rows g / g+8, k pairs)
            const int r0 = (w * 16 + g) * XS_STRIDE + kb + tig * 2;
            const int r1 = (w * 16 + g + 8) * XS_STRIDE + kb + tig * 2;
            const uint32_t a0 = *(const uint32_t*)&xs[r0];
            const uint32_t a1 = *(const uint32_t*)&xs[r1];
            const uint32_t a2 = *(const uint32_t*)&xs[r0 + 8];
            const uint32_t a3 = *(const uint32_t*)&xs[r1 + 8];

#pragma unroll
            for (int nt = 0; nt < 8; nt++) {
                const int nrow = (nt * 8 + g) * WS_STRIDE + kglob + tig * 2;
                const uint32_t b0 = *(const uint32_t*)&ws[nrow];
                const uint32_t b1 = *(const uint32_t*)&ws[nrow + 8];
                asm volatile(
                    "mma.sync.aligned.m16n8k16.row.col.f32.f16.f16.f32 "
                    "{%0, %1, %2, %3}, {%4, %5, %6, %7}, {%8, %9}, "
                    "{%0, %1, %2, %3};"
                    : "+f"(acc[nt][0]), "+f"(acc[nt][1]),
                      "+f"(acc[nt][2]), "+f"(acc[nt][3])
                    : "r"(a0), "r"(a1), "r"(a2), "r"(a3), "r"(b0), "r"(b1));
            }
        }
        __syncthreads();
    }

    // ---- epilogue: bias add, store to g_h ----
    const int row0 = block_row + w * 16 + g;
    const int row1 = row0 + 8;
#pragma unroll
    for (int nt = 0; nt < 8; nt++) {
        const int col = nt * 8 + 2 * tig;
        const float bx = b[col], by = b[col + 1];
        if (row0 < N)
            *(float2*)(g_h + (size_t)row0 * N_OUT + col) =
                make_float2(acc[nt][0] + bx, acc[nt][1] + by);
        if (row1 < N)
            *(float2*)(g_h + (size_t)row1 * N_OUT + col) =
                make_float2(acc[nt][2] + bx, acc[nt][3] + by);
    }
}

// ===========================================================================
// Gather aggregation + fused ELU: out[i] = elu(sum_e val[e] * h[col[e]])
// 16 lanes per node, one float4 slice each; edge loop unrolled x4 for MLP.
// ===========================================================================
__global__ void __launch_bounds__(256) gather_kernel(float* __restrict__ out, int N)
{
    const int gtid = blockIdx.x * blockDim.x + threadIdx.x;
    const int node = gtid >> 4;
    const int lane = gtid & 15;
    if (node >= N) return;

    int beg = g_rowptr[node];
    const int end = g_rowptr[node + 1];

    float4 acc = make_float4(0.f, 0.f, 0.f, 0.f);

    for (; beg + 4 <= end; beg += 4) {
        const int   c0 = g_ecol[beg],     c1 = g_ecol[beg + 1];
        const int   c2 = g_ecol[beg + 2], c3 = g_ecol[beg + 3];
        const float v0 = g_eval[beg],     v1 = g_eval[beg + 1];
        const float v2 = g_eval[beg + 2], v3 = g_eval[beg + 3];
        const float4 m0 = *((const float4*)(g_h + (size_t)c0 * N_OUT) + lane);
        const float4 m1 = *((const float4*)(g_h + (size_t)c1 * N_OUT) + lane);
        const float4 m2 = *((const float4*)(g_h + (size_t)c2 * N_OUT) + lane);
        const float4 m3 = *((const float4*)(g_h + (size_t)c3 * N_OUT) + lane);
        acc.x += v0 * m0.x; acc.y += v0 * m0.y; acc.z += v0 * m0.z; acc.w += v0 * m0.w;
        acc.x += v1 * m1.x; acc.y += v1 * m1.y; acc.z += v1 * m1.z; acc.w += v1 * m1.w;
        acc.x += v2 * m2.x; acc.y += v2 * m2.y; acc.z += v2 * m2.z; acc.w += v2 * m2.w;
        acc.x += v3 * m3.x; acc.y += v3 * m3.y; acc.z += v3 * m3.z; acc.w += v3 * m3.w;
    }
    for (; beg < end; beg++) {
        const int   c = g_ecol[beg];
        const float v = g_eval[beg];
        const float4 m = *((const float4*)(g_h + (size_t)c * N_OUT) + lane);
        acc.x += v * m.x; acc.y += v * m.y; acc.z += v * m.z; acc.w += v * m.w;
    }

    // ELU (alpha=1)
    acc.x = acc.x > 0.f ? acc.x : expm1f(acc.x);
    acc.y = acc.y > 0.f ? acc.y : expm1f(acc.y);
    acc.z = acc.z > 0.f ? acc.z : expm1f(acc.z);
    acc.w = acc.w > 0.f ? acc.w : expm1f(acc.w);

    *((float4*)(out + (size_t)node * N_OUT) + lane) = acc;
}

// ===========================================================================
extern "C" void kernel_launch(void* const* d_in, const int* in_sizes, int n_in,
                              void* d_out, int out_size)
{
    const float* x  = (const float*)d_in[0];
    const int*   er = (const int*)  d_in[1];
    const int*   ec = (const int*)  d_in[2];
    const float* ev = (const float*)d_in[3];
    const float* W  = (const float*)d_in[4];
    const float* b  = (const float*)d_in[5];
    float* out = (float*)d_out;

    const int N = in_sizes[0] / N_IN;   // 100000
    const int E = in_sizes[1];          // 1600000
    const int NB = (N + SCAN_BLK - 1) / SCAN_BLK;   // 196

    static bool attr_set = false;
    if (!attr_set) {
        cudaFuncSetAttribute(gemm_mma_kernel,
                             cudaFuncAttributeMaxDynamicSharedMemorySize, GEMM_SMEM);
        attr_set = true;
    }

    // --- CSR build ---
    deg_zero_kernel<<<(N + 511) / 512, 512>>>(N);
    hist_kernel<<<(E + 255) / 256, 256>>>(er, E);
    bsum_kernel<<<NB, SCAN_BLK>>>(N);
    scan_bsum_kernel<<<1, 256>>>(NB);
    scan_local_kernel<<<NB, SCAN_BLK>>>(N, E);
    fill_kernel<<<(E + 255) / 256, 256>>>(er, ec, ev, E);

    // --- W^T fp16 prep + GEMM: h = x @ W + b ---
    wht_kernel<<<(N_OUT * N_IN + 255) / 256, 256>>>(W);
    gemm_mma_kernel<<<(N + TM - 1) / TM, 256, GEMM_SMEM>>>(x, b, N);

    // --- out = elu(A @ h) via CSR gather ---
    {
        long long total = (long long)N * 16;
        int blocks = (int)((total + 255) / 256);
        gather_kernel<<<blocks, 256>>>(out, N);
    }
}

// round 7
// speedup vs baseline: 1.4792x; 1.0467x over previous
#include <cuda_runtime.h>
#include <cuda_fp16.h>
#include <cuda_bf16.h>
#include <cstdint>
#include <math.h>

#define N_IN   256
#define N_OUT  64
#define TM     128            // rows per GEMM CTA
#define XS_STRIDE 72          // x tile smem stride in halves (64 k + pad)
#define WS_STRIDE 264         // W^T smem stride in halves (256 k + pad)

#define MAX_N  100000
#define MAX_E  1600000
#define SCAN_BLK 512

// Scratch
__device__ uint4    g_hh[MAX_N * 8];         // h in fp16: 64 halves = 8 uint4 per row
__device__ __half   g_wht[N_OUT * N_IN];     // W^T in fp16: [n][k]
__device__ int      g_deg[MAX_N];            // zero at module load; restored by scan_local
__device__ int      g_bsum[256];
__device__ int      g_scan_ctr;
__device__ int      g_rowptr[MAX_N + 1];
__device__ int      g_cursor[MAX_N];
__device__ int      g_ecol[MAX_E];
__device__ float    g_eval[MAX_E];

// dynamic smem: xs[128][72] halves + ws[64][264] halves
#define XS_HALVES (TM * XS_STRIDE)           // 9216
#define WS_HALVES (N_OUT * WS_STRIDE)        // 16896
#define GEMM_SMEM ((XS_HALVES + WS_HALVES) * 2)   // 52224 B

// ===========================================================================
// CSR build (4 launches)
// ===========================================================================
__global__ void hist_kernel(const int* __restrict__ rows, int E) {
    int e = blockIdx.x * blockDim.x + threadIdx.x;
    if (e < E) atomicAdd(&g_deg[rows[e]], 1);
}

// block sums + fused last-block exclusive scan of the block sums
__global__ void __launch_bounds__(SCAN_BLK) bsum_scan_kernel(int n, int nb) {
    __shared__ int s[SCAN_BLK];
    __shared__ int is_last;
    const int t = threadIdx.x;
    const int i = blockIdx.x * SCAN_BLK + t;
    s[t] = (i < n) ? g_deg[i] : 0;
    __syncthreads();
#pragma unroll
    for (int st = SCAN_BLK / 2; st > 0; st >>= 1) {
        if (t < st) s[t] += s[t + st];
        __syncthreads();
    }
    if (t == 0) {
        g_bsum[blockIdx.x] = s[0];
        __threadfence();
        int old = atomicAdd(&g_scan_ctr, 1);
        is_last = (old == nb - 1) ? 1 : 0;
    }
    __syncthreads();
    if (is_last) {
        // exclusive scan of nb (<=256) block sums, Hillis-Steele on 256 lanes
        const int v = (t < nb) ? g_bsum[t] : 0;
        if (t < 256) s[t] = v;
        __syncthreads();
#pragma unroll
        for (int off = 1; off < 256; off <<= 1) {
            int add = (t >= off && t < 256) ? s[t - off] : 0;
            __syncthreads();
            if (t < 256) s[t] += add;
            __syncthreads();
        }
        if (t < nb) g_bsum[t] = s[t] - v;
        if (t == 0) g_scan_ctr = 0;   // reset for next call
    }
}

__global__ void __launch_bounds__(SCAN_BLK) scan_local_kernel(int n, int E) {
    __shared__ int s[SCAN_BLK];
    const int t = threadIdx.x;
    const int i = blockIdx.x * SCAN_BLK + t;
    const int v = (i < n) ? g_deg[i] : 0;
    if (i < n) g_deg[i] = 0;          // restore invariant for next call
    s[t] = v;
    __syncthreads();
#pragma unroll
    for (int off = 1; off < SCAN_BLK; off <<= 1) {
        int add = (t >= off) ? s[t - off] : 0;
        __syncthreads();
        s[t] += add;
        __syncthreads();
    }
    const int excl = s[t] - v;
    const int base = g_bsum[blockIdx.x];
    if (i < n) {
        g_rowptr[i] = base + excl;
        g_cursor[i] = base + excl;
    }
    if (i == n - 1) g_rowptr[n] = E;
}

__global__ void fill_kernel(const int* __restrict__ rows,
                            const int* __restrict__ cols,
                            const float* __restrict__ vals, int E) {
    int e = blockIdx.x * blockDim.x + threadIdx.x;
    if (e < E) {
        int p = atomicAdd(&g_cursor[rows[e]], 1);
        g_ecol[p] = cols[e];
        g_eval[p] = vals[e];
    }
}

// ===========================================================================
// W^T fp16 prep: g_wht[n][k] = fp16(W[k][n])
// ===========================================================================
__global__ void wht_kernel(const float* __restrict__ W) {
    int i = blockIdx.x * blockDim.x + threadIdx.x;
    if (i < N_OUT * N_IN) {
        const int n = i >> 8;
        const int k = i & 255;
        g_wht[i] = __float2half_rn(W[(size_t)k * N_OUT + n]);
    }
}

// ===========================================================================
// GEMM via mma.sync m16n8k16 fp16 (fp32 accum): h[N,64] = x[N,256]@W + b
// Output stored as fp16 rows (128B each) in g_hh.
// ===========================================================================
__global__ void __launch_bounds__(256) gemm_mma_kernel(
    const float* __restrict__ x, const float* __restrict__ b, int N)
{
    extern __shared__ uint16_t smem_h[];
    uint16_t* xs = smem_h;               // [128][XS_STRIDE]
    uint16_t* ws = smem_h + XS_HALVES;   // [64][WS_STRIDE]

    const int tid  = threadIdx.x;
    const int w    = tid >> 5;
    const int lane = tid & 31;
    const int g    = lane >> 2;          // 0..7
    const int tig  = lane & 3;           // 0..3
    const int block_row = blockIdx.x * TM;

    // ---- stage W^T: 64 rows x 256 k halves, uint4 copy ----
    for (int i = tid; i < N_OUT * 32; i += 256) {
        const int n = i >> 5;
        const int j = i & 31;
        *(uint4*)&ws[n * WS_STRIDE + j * 8] = ((const uint4*)g_wht)[n * 32 + j];
    }

    float acc[8][4];
#pragma unroll
    for (int nt = 0; nt < 8; nt++)
#pragma unroll
        for (int j = 0; j < 4; j++) acc[nt][j] = 0.f;

    for (int kc = 0; kc < 4; kc++) {
        // ---- stage x chunk: 128 rows x 64 k, fp32 -> fp16 ----
#pragma unroll
        for (int p = 0; p < 8; p++) {
            const int id  = tid + p * 256;
            const int row = id >> 4;
            const int f4  = id & 15;
            int grow = block_row + row;
            if (grow >= N) grow = N - 1;                  // clamp, result unused
            float4 v = *(const float4*)(x + (size_t)grow * N_IN + kc * 64 + f4 * 4);
            __half2 h01 = __float22half2_rn(make_float2(v.x, v.y));
            __half2 h23 = __float22half2_rn(make_float2(v.z, v.w));
            uint2 pk;
            pk.x = *(const uint32_t*)&h01;
            pk.y = *(const uint32_t*)&h23;
            *(uint2*)&xs[row * XS_STRIDE + f4 * 4] = pk;
        }
        __syncthreads();

#pragma unroll
        for (int k16 = 0; k16 < 4; k16++) {
            const int kb = k16 * 16;
            const int kglob = kc * 64 + kb;

            const int r0 = (w * 16 + g) * XS_STRIDE + kb + tig * 2;
            const int r1 = (w * 16 + g + 8) * XS_STRIDE + kb + tig * 2;
            const uint32_t a0 = *(const uint32_t*)&xs[r0];
            const uint32_t a1 = *(const uint32_t*)&xs[r1];
            const uint32_t a2 = *(const uint32_t*)&xs[r0 + 8];
            const uint32_t a3 = *(const uint32_t*)&xs[r1 + 8];

#pragma unroll
            for (int nt = 0; nt < 8; nt++) {
                const int nrow = (nt * 8 + g) * WS_STRIDE + kglob + tig * 2;
                const uint32_t b0 = *(const uint32_t*)&ws[nrow];
                const uint32_t b1 = *(const uint32_t*)&ws[nrow + 8];
                asm volatile(
                    "mma.sync.aligned.m16n8k16.row.col.f32.f16.f16.f32 "
                    "{%0, %1, %2, %3}, {%4, %5, %6, %7}, {%8, %9}, "
                    "{%0, %1, %2, %3};"
                    : "+f"(acc[nt][0]), "+f"(acc[nt][1]),
                      "+f"(acc[nt][2]), "+f"(acc[nt][3])
                    : "r"(a0), "r"(a1), "r"(a2), "r"(a3), "r"(b0), "r"(b1));
            }
        }
        __syncthreads();
    }

    // ---- epilogue: bias add (fp32), convert to fp16, store to g_hh ----
    __half* hh = (__half*)g_hh;
    const int row0 = block_row + w * 16 + g;
    const int row1 = row0 + 8;
#pragma unroll
    for (int nt = 0; nt < 8; nt++) {
        const int col = nt * 8 + 2 * tig;
        const float bx = b[col], by = b[col + 1];
        if (row0 < N) {
            __half2 h = __float22half2_rn(
                make_float2(acc[nt][0] + bx, acc[nt][1] + by));
            *(uint32_t*)(hh + (size_t)row0 * N_OUT + col) = *(const uint32_t*)&h;
        }
        if (row1 < N) {
            __half2 h = __float22half2_rn(
                make_float2(acc[nt][2] + bx, acc[nt][3] + by));
            *(uint32_t*)(hh + (size_t)row1 * N_OUT + col) = *(const uint32_t*)&h;
        }
    }
}

// ===========================================================================
// Gather aggregation + fused ELU: out[i] = elu(sum_e val[e] * h[col[e]])
// 8 lanes per node; each lane owns 8 halves (one uint4 = 16B) of the row.
// ===========================================================================
__device__ __forceinline__ void acc_q(float* acc, float v, uint4 q) {
    float2 f;
    f = __half22float2(*(__half2*)&q.x); acc[0] += v * f.x; acc[1] += v * f.y;
    f = __half22float2(*(__half2*)&q.y); acc[2] += v * f.x; acc[3] += v * f.y;
    f = __half22float2(*(__half2*)&q.z); acc[4] += v * f.x; acc[5] += v * f.y;
    f = __half22float2(*(__half2*)&q.w); acc[6] += v * f.x; acc[7] += v * f.y;
}

__global__ void __launch_bounds__(256) gather_kernel(float* __restrict__ out, int N)
{
    const int gtid = blockIdx.x * blockDim.x + threadIdx.x;
    const int node = gtid >> 3;
    const int lane = gtid & 7;
    if (node >= N) return;

    int beg = g_rowptr[node];
    const int end = g_rowptr[node + 1];

    float acc[8];
#pragma unroll
    for (int j = 0; j < 8; j++) acc[j] = 0.f;

    for (; beg + 4 <= end; beg += 4) {
        const int   c0 = g_ecol[beg],     c1 = g_ecol[beg + 1];
        const int   c2 = g_ecol[beg + 2], c3 = g_ecol[beg + 3];
        const float v0 = g_eval[beg],     v1 = g_eval[beg + 1];
        const float v2 = g_eval[beg + 2], v3 = g_eval[beg + 3];
        const uint4 q0 = g_hh[(size_t)c0 * 8 + lane];
        const uint4 q1 = g_hh[(size_t)c1 * 8 + lane];
        const uint4 q2 = g_hh[(size_t)c2 * 8 + lane];
        const uint4 q3 = g_hh[(size_t)c3 * 8 + lane];
        acc_q(acc, v0, q0);
        acc_q(acc, v1, q1);
        acc_q(acc, v2, q2);
        acc_q(acc, v3, q3);
    }
    for (; beg < end; beg++) {
        const int   c = g_ecol[beg];
        const float v = g_eval[beg];
        const uint4 q = g_hh[(size_t)c * 8 + lane];
        acc_q(acc, v, q);
    }

    // ELU (alpha=1)
#pragma unroll
    for (int j = 0; j < 8; j++)
        acc[j] = acc[j] > 0.f ? acc[j] : expm1f(acc[j]);

    float* o = out + (size_t)node * N_OUT + lane * 8;
    *(float4*)(o)     = make_float4(acc[0], acc[1], acc[2], acc[3]);
    *(float4*)(o + 4) = make_float4(acc[4], acc[5], acc[6], acc[7]);
}

// ===========================================================================
extern "C" void kernel_launch(void* const* d_in, const int* in_sizes, int n_in,
                              void* d_out, int out_size)
{
    const float* x  = (const float*)d_in[0];
    const int*   er = (const int*)  d_in[1];
    const int*   ec = (const int*)  d_in[2];
    const float* ev = (const float*)d_in[3];
    const float* W  = (const float*)d_in[4];
    const float* b  = (const float*)d_in[5];
    float* out = (float*)d_out;

    const int N = in_sizes[0] / N_IN;   // 100000
    const int E = in_sizes[1];          // 1600000
    const int NB = (N + SCAN_BLK - 1) / SCAN_BLK;   // 196

    static bool attr_set = false;
    if (!attr_set) {
        cudaFuncSetAttribute(gemm_mma_kernel,
                             cudaFuncAttributeMaxDynamicSharedMemorySize, GEMM_SMEM);
        attr_set = true;
    }

    // --- CSR build (deg assumed 0 at entry; restored by scan_local) ---
    hist_kernel<<<(E + 255) / 256, 256>>>(er, E);
    bsum_scan_kernel<<<NB, SCAN_BLK>>>(N, NB);
    scan_local_kernel<<<NB, SCAN_BLK>>>(N, E);
    fill_kernel<<<(E + 255) / 256, 256>>>(er, ec, ev, E);

    // --- W^T fp16 prep + GEMM: h = x @ W + b (h stored fp16) ---
    wht_kernel<<<(N_OUT * N_IN + 255) / 256, 256>>>(W);
    gemm_mma_kernel<<<(N + TM - 1) / TM, 256, GEMM_SMEM>>>(x, b, N);

    // --- out = elu(A @ h) via CSR gather ---
    {
        long long total = (long long)N * 8;
        int blocks = (int)((total + 255) / 256);
        gather_kernel<<<blocks, 256>>>(out, N);
    }
}